// round 11
// baseline (speedup 1.0000x reference)
#include <cuda_runtime.h>
#include <math.h>

#define B_DIM 128
#define T_DIM 4096
#define C_DIM 64
#define N_KNOT 6

// -------- scratch & constants (no allocation allowed) --------
__device__ float d_LU[N_KNOT][N_KNOT];   // netlib sgetf2 packed L(unit)+U
__device__ float d_Uinv[N_KNOT];         // fl(1/U[k][k])
__device__ int   d_perm[N_KNOT];
__device__ float d_scratch[(size_t)B_DIM * C_DIM * T_DIM]; // [B,C,T], in-place

// reciprocal constants (correctly-rounded host folds, same as XLA's rewrite)
#define R819   (1.0f / 819.0f)
#define R6C    (1.0f / 6.0f)
#define R4914  (1.0f / 4914.0f)

// -------- setup: netlib sgetf2 (recip-scale + fma sger), fp32 --------
__global__ void setup_kernel() {
    if (threadIdx.x != 0 || blockIdx.x != 0) return;
    float A[N_KNOT][N_KNOT];
    for (int i = 0; i < N_KNOT; i++)
        for (int j = 0; j < N_KNOT; j++) A[i][j] = 0.0f;
    const float h = 819.0f;
    A[0][0] = -1.0f; A[0][1] = 2.0f; A[0][2] = -1.0f;
    for (int i = 1; i <= 4; i++) { A[i][i-1] = h; A[i][i] = 4.0f*h; A[i][i+1] = h; }
    A[5][3] = -1.0f; A[5][4] = 2.0f; A[5][5] = -1.0f;

    int ipiv[N_KNOT];
    for (int j = 0; j < N_KNOT; j++) {
        int p = j;
        float best = fabsf(A[j][j]);
        for (int i = j + 1; i < N_KNOT; i++) {
            float v = fabsf(A[i][j]);
            if (v > best) { best = v; p = i; }
        }
        ipiv[j] = p;
        if (p != j) {
            for (int k = 0; k < N_KNOT; k++) {
                float t = A[j][k]; A[j][k] = A[p][k]; A[p][k] = t;
            }
        }
        float r = __fdiv_rn(1.0f, A[j][j]);
        for (int i = j + 1; i < N_KNOT; i++)
            A[i][j] = __fmul_rn(A[i][j], r);
        for (int k = j + 1; k < N_KNOT; k++) {
            float temp = -A[j][k];
            for (int i = j + 1; i < N_KNOT; i++)
                A[i][k] = __fmaf_rn(A[i][j], temp, A[i][k]);
        }
    }
    int perm[N_KNOT];
    for (int i = 0; i < N_KNOT; i++) perm[i] = i;
    for (int j = 0; j < N_KNOT; j++) {
        int p = ipiv[j];
        int t = perm[j]; perm[j] = perm[p]; perm[p] = t;
    }
    for (int i = 0; i < N_KNOT; i++) {
        d_perm[i] = perm[i];
        for (int j = 0; j < N_KNOT; j++) d_LU[i][j] = A[i][j];
        d_Uinv[i] = __fdiv_rn(1.0f, A[i][i]);
    }
}

// -------- transpose [B,T,C] -> [B,C,T] --------
__global__ void transpose_btc_to_bct(const float* __restrict__ in, float* __restrict__ out) {
    __shared__ float tile[32][33];
    int b = blockIdx.z;
    int t0 = blockIdx.x * 32;
    int c0 = blockIdx.y * 32;
    int tx = threadIdx.x, ty = threadIdx.y;
    const float* inb = in + (size_t)b * T_DIM * C_DIM;
    float* outb = out + (size_t)b * T_DIM * C_DIM;
    #pragma unroll
    for (int i = 0; i < 32; i += 8)
        tile[ty + i][tx] = inb[(size_t)(t0 + ty + i) * C_DIM + (c0 + tx)];
    __syncthreads();
    #pragma unroll
    for (int i = 0; i < 32; i += 8)
        outb[(size_t)(c0 + ty + i) * T_DIM + (t0 + tx)] = tile[tx][ty + i];
}

// -------- transpose [B,C,T] -> [B,T,C] --------
__global__ void transpose_bct_to_btc(const float* __restrict__ in, float* __restrict__ out) {
    __shared__ float tile[32][33];
    int b = blockIdx.z;
    int t0 = blockIdx.x * 32;
    int c0 = blockIdx.y * 32;
    int tx = threadIdx.x, ty = threadIdx.y;
    const float* inb = in + (size_t)b * T_DIM * C_DIM;
    float* outb = out + (size_t)b * T_DIM * C_DIM;
    #pragma unroll
    for (int i = 0; i < 32; i += 8)
        tile[ty + i][tx] = inb[(size_t)(c0 + ty + i) * T_DIM + (t0 + tx)];
    __syncthreads();
    #pragma unroll
    for (int i = 0; i < 32; i += 8)
        outb[(size_t)(t0 + ty + i) * C_DIM + (c0 + tx)] = tile[tx][ty + i];
}

// -------- main per-series kernel (C1 numeric path, monotone fast-path search) --------
__global__ __launch_bounds__(256)
void warp_interp_kernel(const float* __restrict__ warps,
                        float* __restrict__ series /* [B,C,T], in-place */) {
    __shared__ float s_xp[T_DIM];
    __shared__ float s_fp[T_DIM];
    __shared__ float s_y[N_KNOT];
    __shared__ float s_M[N_KNOT];

    const int c = blockIdx.x;
    const int b = blockIdx.y;
    const int tid = threadIdx.x;
    float* row = series + ((size_t)b * C_DIM + c) * T_DIM;

    if (tid == 0) {
        float r[N_KNOT], y[N_KNOT];
        #pragma unroll
        for (int k = 0; k < N_KNOT; k++)
            r[k] = warps[((size_t)b * N_KNOT + k) * C_DIM + c];   // random_warps[b,k,c]
        #pragma unroll
        for (int k = 0; k < N_KNOT; k++)
            y[k] = __fmul_rn(819.0f * (float)k, r[k]);            // y = w*r

        // rhs[i] = (6*((y[i+1]-2*y[i]) + y[i-1])) * fl(1/819)
        float rhs[N_KNOT];
        rhs[0] = 0.0f; rhs[5] = 0.0f;
        #pragma unroll
        for (int i = 1; i <= 4; i++) {
            float t1 = __fmul_rn(2.0f, y[i]);
            float t2 = __fsub_rn(y[i + 1], t1);
            float t3 = __fadd_rn(t2, y[i - 1]);
            float t4 = __fmul_rn(6.0f, t3);
            rhs[i] = __fmul_rn(t4, R819);
        }

        // P*b gather, then axpy fwd (unit L) + axpy bwd with recip-mult diag
        float bb[N_KNOT];
        #pragma unroll
        for (int i = 0; i < N_KNOT; i++) bb[i] = rhs[d_perm[i]];
        #pragma unroll
        for (int k = 0; k < N_KNOT; k++) {
            if (bb[k] != 0.0f) {
                #pragma unroll
                for (int i = k + 1; i < N_KNOT; i++)
                    bb[i] = __fmaf_rn(-bb[k], d_LU[i][k], bb[i]);
            }
        }
        #pragma unroll
        for (int k = N_KNOT - 1; k >= 0; k--) {
            if (bb[k] != 0.0f) {
                bb[k] = __fmul_rn(bb[k], d_Uinv[k]);
                #pragma unroll
                for (int i = 0; i < k; i++)
                    bb[i] = __fmaf_rn(-bb[k], d_LU[i][k], bb[i]);
            }
        }
        #pragma unroll
        for (int k = 0; k < N_KNOT; k++) { s_y[k] = y[k]; s_M[k] = bb[k]; }
    }
    __syncthreads();

    // tw evaluator, frozen op order (XLA recip-mult constant rewrite)
    auto eval_tw = [&](int idx, float t) -> float {
        const float y0 = s_y[idx], y1 = s_y[idx + 1];
        const float M0 = s_M[idx], M1 = s_M[idx + 1];
        float a  = __fsub_rn(y1, y0);
        float bq = __fmul_rn(a, R819);
        float cq = __fmul_rn(2.0f, M0);
        float dq = __fadd_rn(cq, M1);
        float eq = __fmul_rn(819.0f, dq);
        float fq2 = __fmul_rn(eq, R6C);
        float c1 = __fsub_rn(bq, fq2);
        float g1 = __fmul_rn(t, c1);
        float s1 = __fadd_rn(y0, g1);
        float tt = __fmul_rn(t, t);
        float m02 = __fmul_rn(M0, 0.5f);
        float q1 = __fmul_rn(tt, m02);
        float s2 = __fadd_rn(s1, q1);
        float ttt = __fmul_rn(tt, t);
        float dm = __fsub_rn(M1, M0);
        float kk = __fmul_rn(dm, R4914);
        float q2 = __fmul_rn(ttt, kk);
        return __fadd_rn(s2, q2);
    };

    const float scale = __fdiv_rn(4095.0f, eval_tw(4, 819.0f));

    // ---- fill fp (strided, coalesced LDG) ----
    for (int j = tid; j < T_DIM; j += 256) s_fp[j] = row[j];

    // ---- fill xp: 16 CONSECUTIVE values per thread, kept in regs for mono check ----
    const int j0 = tid * 16;
    float xv[16];
    #pragma unroll
    for (int k = 0; k < 16; k++) {
        const float xq = (float)(j0 + k);
        int idx = (int)__fmul_rn(xq, R819);              // identical arithmetic
        idx = idx < 0 ? 0 : (idx > 4 ? 4 : idx);
        const float t = __fsub_rn(xq, 819.0f * (float)idx);
        float tw = eval_tw(idx, t);
        float xpv = __fmul_rn(scale, tw);
        xpv = fminf(fmaxf(xpv, 0.0f), 4095.0f);
        xv[k] = xpv;
        s_xp[j0 + k] = xpv;
    }
    int mono = 1;
    #pragma unroll
    for (int k = 0; k < 15; k++) mono &= (xv[k] <= xv[k + 1]);
    __syncthreads();

    if (j0 + 16 < T_DIM) mono &= (xv[15] <= s_xp[j0 + 16]);
    const int allmono = __syncthreads_and(mono);

    const float xp0 = s_xp[0],       xpN = s_xp[T_DIM - 1];
    const float fp0 = s_fp[0],       fpN = s_fp[T_DIM - 1];

    if (allmono) {
        // ---- FAST PATH: xp non-decreasing => scan-search == standard insertion ----
        // One bisection for q=j0, then forward-walk (insertion point monotone in q).
        const float fq0 = (float)j0;
        int lo = 0, hi = T_DIM;
        #pragma unroll
        for (int s = 0; s < 13; s++) {
            const int mid = (lo + hi) >> 1;
            const bool go_left = fq0 < s_xp[mid];
            lo = go_left ? lo : mid;
            hi = go_left ? mid : hi;
        }
        int ins = hi;                                    // first idx with xp[idx] > q

        #pragma unroll
        for (int k = 0; k < 16; k++) {
            const float fq = (float)(j0 + k);
            if (k > 0) {
                while (ins < T_DIM && s_xp[ins] <= fq) ins++;
            }
            int i = ins;
            i = i < 1 ? 1 : (i > T_DIM - 1 ? T_DIM - 1 : i);

            const float x0 = s_xp[i - 1], x1 = s_xp[i];
            const float f0 = s_fp[i - 1], f1 = s_fp[i];
            const float dx = __fsub_rn(x1, x0);
            float f;
            if (fabsf(dx) <= 1.4210855e-14f) {
                f = f0;
            } else {
                const float df    = __fsub_rn(f1, f0);
                const float delta = __fsub_rn(fq, x0);
                const float ratio = __fdiv_rn(delta, dx);
                const float prod  = __fmul_rn(ratio, df);
                f = __fadd_rn(f0, prod);
            }
            if (fq < xp0) f = fp0;
            if (fq > xpN) f = fpN;
            xv[k] = f;                                   // reuse regs for results
        }
        // coalesced-enough vector writes: warp covers contiguous 2KB
        float4* rp = reinterpret_cast<float4*>(row + j0);
        rp[0] = make_float4(xv[0],  xv[1],  xv[2],  xv[3]);
        rp[1] = make_float4(xv[4],  xv[5],  xv[6],  xv[7]);
        rp[2] = make_float4(xv[8],  xv[9],  xv[10], xv[11]);
        rp[3] = make_float4(xv[12], xv[13], xv[14], xv[15]);
    } else {
        // ---- SLOW PATH: exact jnp scan replica per query (strided, conflict-free) ----
        for (int q = tid; q < T_DIM; q += 256) {
            const float fq = (float)q;
            int lo = 0, hi = T_DIM;
            #pragma unroll
            for (int s = 0; s < 13; s++) {
                const int mid = (lo + hi) >> 1;
                const bool go_left = fq < s_xp[mid];
                lo = go_left ? lo : mid;
                hi = go_left ? mid : hi;
            }
            int i = hi;
            i = i < 1 ? 1 : (i > T_DIM - 1 ? T_DIM - 1 : i);

            const float x0 = s_xp[i - 1], x1 = s_xp[i];
            const float f0 = s_fp[i - 1], f1 = s_fp[i];
            const float dx = __fsub_rn(x1, x0);
            float f;
            if (fabsf(dx) <= 1.4210855e-14f) {
                f = f0;
            } else {
                const float df    = __fsub_rn(f1, f0);
                const float delta = __fsub_rn(fq, x0);
                const float ratio = __fdiv_rn(delta, dx);
                const float prod  = __fmul_rn(ratio, df);
                f = __fadd_rn(f0, prod);
            }
            if (fq < xp0) f = fp0;
            if (fq > xpN) f = fpN;
            row[q] = f;
        }
    }
}

extern "C" void kernel_launch(void* const* d_in, const int* in_sizes, int n_in,
                              void* d_out, int out_size) {
    const float* x = (const float*)d_in[0];
    const float* w = (const float*)d_in[1];
    if (n_in >= 2 && in_sizes[0] < in_sizes[1]) {        // x is the big tensor
        x = (const float*)d_in[1];
        w = (const float*)d_in[0];
    }
    float* out = (float*)d_out;

    float* scratch = nullptr;
    cudaGetSymbolAddress((void**)&scratch, d_scratch);

    setup_kernel<<<1, 1>>>();

    dim3 tb(32, 8);
    dim3 gT(T_DIM / 32, C_DIM / 32, B_DIM);
    transpose_btc_to_bct<<<gT, tb>>>(x, scratch);

    dim3 gW(C_DIM, B_DIM);
    warp_interp_kernel<<<gW, 256>>>(w, scratch);

    transpose_bct_to_btc<<<gT, tb>>>(scratch, out);
}

// round 12
// speedup vs baseline: 1.3530x; 1.3530x over previous
#include <cuda_runtime.h>
#include <math.h>

#define B_DIM 128
#define T_DIM 4096
#define C_DIM 64
#define N_KNOT 6

// -------- scratch & constants (no allocation allowed) --------
__device__ float d_LU[N_KNOT][N_KNOT];   // netlib sgetf2 packed L(unit)+U
__device__ float d_Uinv[N_KNOT];         // fl(1/U[k][k])
__device__ int   d_perm[N_KNOT];
__device__ float d_scratch[(size_t)B_DIM * C_DIM * T_DIM]; // [B,C,T], in-place

// reciprocal constants (correctly-rounded host folds, same as XLA's rewrite)
#define R819   (1.0f / 819.0f)
#define R6C    (1.0f / 6.0f)
#define R4914  (1.0f / 4914.0f)

// dynamic smem layout: xp[4096] fp[4096] ins[4096] tot[256] wsum[8] y[6] M[6]
#define SMEM_BYTES ((3 * T_DIM + 256 + 8 + 12) * 4)

// -------- setup: netlib sgetf2 (recip-scale + fma sger), fp32 --------
__global__ void setup_kernel() {
    if (threadIdx.x != 0 || blockIdx.x != 0) return;
    float A[N_KNOT][N_KNOT];
    for (int i = 0; i < N_KNOT; i++)
        for (int j = 0; j < N_KNOT; j++) A[i][j] = 0.0f;
    const float h = 819.0f;
    A[0][0] = -1.0f; A[0][1] = 2.0f; A[0][2] = -1.0f;
    for (int i = 1; i <= 4; i++) { A[i][i-1] = h; A[i][i] = 4.0f*h; A[i][i+1] = h; }
    A[5][3] = -1.0f; A[5][4] = 2.0f; A[5][5] = -1.0f;

    int ipiv[N_KNOT];
    for (int j = 0; j < N_KNOT; j++) {
        int p = j;
        float best = fabsf(A[j][j]);
        for (int i = j + 1; i < N_KNOT; i++) {
            float v = fabsf(A[i][j]);
            if (v > best) { best = v; p = i; }
        }
        ipiv[j] = p;
        if (p != j) {
            for (int k = 0; k < N_KNOT; k++) {
                float t = A[j][k]; A[j][k] = A[p][k]; A[p][k] = t;
            }
        }
        float r = __fdiv_rn(1.0f, A[j][j]);
        for (int i = j + 1; i < N_KNOT; i++)
            A[i][j] = __fmul_rn(A[i][j], r);
        for (int k = j + 1; k < N_KNOT; k++) {
            float temp = -A[j][k];
            for (int i = j + 1; i < N_KNOT; i++)
                A[i][k] = __fmaf_rn(A[i][j], temp, A[i][k]);
        }
    }
    int perm[N_KNOT];
    for (int i = 0; i < N_KNOT; i++) perm[i] = i;
    for (int j = 0; j < N_KNOT; j++) {
        int p = ipiv[j];
        int t = perm[j]; perm[j] = perm[p]; perm[p] = t;
    }
    for (int i = 0; i < N_KNOT; i++) {
        d_perm[i] = perm[i];
        for (int j = 0; j < N_KNOT; j++) d_LU[i][j] = A[i][j];
        d_Uinv[i] = __fdiv_rn(1.0f, A[i][i]);
    }
}

// -------- transpose [B,T,C] -> [B,C,T] --------
__global__ void transpose_btc_to_bct(const float* __restrict__ in, float* __restrict__ out) {
    __shared__ float tile[32][33];
    int b = blockIdx.z;
    int t0 = blockIdx.x * 32;
    int c0 = blockIdx.y * 32;
    int tx = threadIdx.x, ty = threadIdx.y;
    const float* inb = in + (size_t)b * T_DIM * C_DIM;
    float* outb = out + (size_t)b * T_DIM * C_DIM;
    #pragma unroll
    for (int i = 0; i < 32; i += 8)
        tile[ty + i][tx] = inb[(size_t)(t0 + ty + i) * C_DIM + (c0 + tx)];
    __syncthreads();
    #pragma unroll
    for (int i = 0; i < 32; i += 8)
        outb[(size_t)(c0 + ty + i) * T_DIM + (t0 + tx)] = tile[tx][ty + i];
}

// -------- transpose [B,C,T] -> [B,T,C] --------
__global__ void transpose_bct_to_btc(const float* __restrict__ in, float* __restrict__ out) {
    __shared__ float tile[32][33];
    int b = blockIdx.z;
    int t0 = blockIdx.x * 32;
    int c0 = blockIdx.y * 32;
    int tx = threadIdx.x, ty = threadIdx.y;
    const float* inb = in + (size_t)b * T_DIM * C_DIM;
    float* outb = out + (size_t)b * T_DIM * C_DIM;
    #pragma unroll
    for (int i = 0; i < 32; i += 8)
        tile[ty + i][tx] = inb[(size_t)(c0 + ty + i) * T_DIM + (t0 + tx)];
    __syncthreads();
    #pragma unroll
    for (int i = 0; i < 32; i += 8)
        outb[(size_t)(t0 + ty + i) * C_DIM + (c0 + tx)] = tile[tx][ty + i];
}

// -------- main per-series kernel (C1 numeric path; histogram fast search) --------
__global__ __launch_bounds__(256)
void warp_interp_kernel(const float* __restrict__ warps,
                        float* __restrict__ series /* [B,C,T], in-place */) {
    extern __shared__ unsigned char smem_raw[];
    float* s_xp  = (float*)smem_raw;              // [T_DIM]
    float* s_fp  = s_xp + T_DIM;                  // [T_DIM]
    int*   s_ins = (int*)(s_fp + T_DIM);          // [T_DIM]
    int*   s_tot = s_ins + T_DIM;                 // [256]
    int*   s_wsm = s_tot + 256;                   // [8]
    float* s_y   = (float*)(s_wsm + 8);           // [6]
    float* s_M   = s_y + N_KNOT;                  // [6]

    const int c = blockIdx.x;
    const int b = blockIdx.y;
    const int tid = threadIdx.x;
    float* row = series + ((size_t)b * C_DIM + c) * T_DIM;

    if (tid == 0) {
        float r[N_KNOT], y[N_KNOT];
        #pragma unroll
        for (int k = 0; k < N_KNOT; k++)
            r[k] = warps[((size_t)b * N_KNOT + k) * C_DIM + c];   // random_warps[b,k,c]
        #pragma unroll
        for (int k = 0; k < N_KNOT; k++)
            y[k] = __fmul_rn(819.0f * (float)k, r[k]);            // y = w*r

        // rhs[i] = (6*((y[i+1]-2*y[i]) + y[i-1])) * fl(1/819)
        float rhs[N_KNOT];
        rhs[0] = 0.0f; rhs[5] = 0.0f;
        #pragma unroll
        for (int i = 1; i <= 4; i++) {
            float t1 = __fmul_rn(2.0f, y[i]);
            float t2 = __fsub_rn(y[i + 1], t1);
            float t3 = __fadd_rn(t2, y[i - 1]);
            float t4 = __fmul_rn(6.0f, t3);
            rhs[i] = __fmul_rn(t4, R819);
        }

        // P*b gather, then axpy fwd (unit L) + axpy bwd with recip-mult diag
        float bb[N_KNOT];
        #pragma unroll
        for (int i = 0; i < N_KNOT; i++) bb[i] = rhs[d_perm[i]];
        #pragma unroll
        for (int k = 0; k < N_KNOT; k++) {
            if (bb[k] != 0.0f) {
                #pragma unroll
                for (int i = k + 1; i < N_KNOT; i++)
                    bb[i] = __fmaf_rn(-bb[k], d_LU[i][k], bb[i]);
            }
        }
        #pragma unroll
        for (int k = N_KNOT - 1; k >= 0; k--) {
            if (bb[k] != 0.0f) {
                bb[k] = __fmul_rn(bb[k], d_Uinv[k]);
                #pragma unroll
                for (int i = 0; i < k; i++)
                    bb[i] = __fmaf_rn(-bb[k], d_LU[i][k], bb[i]);
            }
        }
        #pragma unroll
        for (int k = 0; k < N_KNOT; k++) { s_y[k] = y[k]; s_M[k] = bb[k]; }
    }
    __syncthreads();

    // tw evaluator, frozen op order (XLA recip-mult constant rewrite)
    auto eval_tw = [&](int idx, float t) -> float {
        const float y0 = s_y[idx], y1 = s_y[idx + 1];
        const float M0 = s_M[idx], M1 = s_M[idx + 1];
        float a  = __fsub_rn(y1, y0);
        float bq = __fmul_rn(a, R819);
        float cq = __fmul_rn(2.0f, M0);
        float dq = __fadd_rn(cq, M1);
        float eq = __fmul_rn(819.0f, dq);
        float fq2 = __fmul_rn(eq, R6C);
        float c1 = __fsub_rn(bq, fq2);
        float g1 = __fmul_rn(t, c1);
        float s1 = __fadd_rn(y0, g1);
        float tt = __fmul_rn(t, t);
        float m02 = __fmul_rn(M0, 0.5f);
        float q1 = __fmul_rn(tt, m02);
        float s2 = __fadd_rn(s1, q1);
        float ttt = __fmul_rn(tt, t);
        float dm = __fsub_rn(M1, M0);
        float kk = __fmul_rn(dm, R4914);
        float q2 = __fmul_rn(ttt, kk);
        return __fadd_rn(s2, q2);
    };

    const float scale = __fdiv_rn(4095.0f, eval_tw(4, 819.0f));

    // ---- fill fp (strided, coalesced) and zero histogram ----
    for (int j = tid; j < T_DIM; j += 256) {
        s_fp[j] = row[j];
        s_ins[j] = 0;
    }

    // ---- fill xp: 16 consecutive per thread, mono check in registers ----
    const int j0 = tid * 16;
    float xv[16];
    #pragma unroll
    for (int k = 0; k < 16; k++) {
        const float xq = (float)(j0 + k);
        int idx = (int)__fmul_rn(xq, R819);
        idx = idx < 0 ? 0 : (idx > 4 ? 4 : idx);
        const float t = __fsub_rn(xq, 819.0f * (float)idx);
        float tw = eval_tw(idx, t);
        float xpv = __fmul_rn(scale, tw);
        xpv = fminf(fmaxf(xpv, 0.0f), 4095.0f);
        xv[k] = xpv;
        s_xp[j0 + k] = xpv;
    }
    int mono = 1;
    #pragma unroll
    for (int k = 0; k < 15; k++) mono &= (xv[k] <= xv[k + 1]);
    __syncthreads();
    if (j0 + 16 < T_DIM) mono &= (xv[15] <= s_xp[j0 + 16]);
    const int allmono = __syncthreads_and(mono);

    const float xp0 = s_xp[0],       xpN = s_xp[T_DIM - 1];
    const float fp0 = s_fp[0],       fpN = s_fp[T_DIM - 1];

    if (allmono) {
        // ---- FAST PATH (proven ≡ scan-search for monotone xp, R11 bit-match) ----
        // ins(q) = #{i: xp[i] <= q} = inclusive-prefix of hist[c = ceil(xp[i])]
        #pragma unroll
        for (int k = 0; k < 16; k++) {
            int cb = (int)ceilf(xv[k]);                  // 0..4095 (xp clipped)
            atomicAdd(&s_ins[cb], 1);
        }
        __syncthreads();

        // chunked inclusive prefix sum: 16 bins per thread
        int run = 0;
        #pragma unroll
        for (int k = 0; k < 16; k++) {
            run += s_ins[j0 + k];
            s_ins[j0 + k] = run;
        }
        s_tot[tid] = run;
        __syncthreads();

        // block scan of 256 chunk totals (shuffle intra-warp + tiny warp-sum scan)
        int v = s_tot[tid];
        #pragma unroll
        for (int d = 1; d < 32; d <<= 1) {
            int n = __shfl_up_sync(0xFFFFFFFFu, v, d);
            if ((tid & 31) >= d) v += n;
        }
        if ((tid & 31) == 31) s_wsm[tid >> 5] = v;
        __syncthreads();
        if (tid == 0) {
            int acc = 0;
            #pragma unroll
            for (int w = 0; w < 8; w++) { int t = s_wsm[w]; s_wsm[w] = acc; acc += t; }
        }
        __syncthreads();
        const int chunk_excl = (v - s_tot[tid]) + s_wsm[tid >> 5];
        #pragma unroll
        for (int k = 0; k < 16; k++)
            s_ins[j0 + k] += chunk_excl;
        __syncthreads();

        // ---- interp: one LDS lookup per query ----
        for (int q = tid; q < T_DIM; q += 256) {
            const float fq = (float)q;
            int i = s_ins[q];
            i = i < 1 ? 1 : (i > T_DIM - 1 ? T_DIM - 1 : i);

            const float x0 = s_xp[i - 1], x1 = s_xp[i];
            const float f0 = s_fp[i - 1], f1 = s_fp[i];
            const float dx = __fsub_rn(x1, x0);
            float f;
            if (fabsf(dx) <= 1.4210855e-14f) {
                f = f0;
            } else {
                const float df    = __fsub_rn(f1, f0);
                const float delta = __fsub_rn(fq, x0);
                const float ratio = __fdiv_rn(delta, dx);
                const float prod  = __fmul_rn(ratio, df);
                f = __fadd_rn(f0, prod);
            }
            if (fq < xp0) f = fp0;
            if (fq > xpN) f = fpN;
            row[q] = f;
        }
    } else {
        // ---- SLOW PATH: exact jnp scan replica per query ----
        for (int q = tid; q < T_DIM; q += 256) {
            const float fq = (float)q;
            int lo = 0, hi = T_DIM;
            #pragma unroll
            for (int s = 0; s < 13; s++) {
                const int mid = (lo + hi) >> 1;
                const bool go_left = fq < s_xp[mid];
                lo = go_left ? lo : mid;
                hi = go_left ? mid : hi;
            }
            int i = hi;
            i = i < 1 ? 1 : (i > T_DIM - 1 ? T_DIM - 1 : i);

            const float x0 = s_xp[i - 1], x1 = s_xp[i];
            const float f0 = s_fp[i - 1], f1 = s_fp[i];
            const float dx = __fsub_rn(x1, x0);
            float f;
            if (fabsf(dx) <= 1.4210855e-14f) {
                f = f0;
            } else {
                const float df    = __fsub_rn(f1, f0);
                const float delta = __fsub_rn(fq, x0);
                const float ratio = __fdiv_rn(delta, dx);
                const float prod  = __fmul_rn(ratio, df);
                f = __fadd_rn(f0, prod);
            }
            if (fq < xp0) f = fp0;
            if (fq > xpN) f = fpN;
            row[q] = f;
        }
    }
}

extern "C" void kernel_launch(void* const* d_in, const int* in_sizes, int n_in,
                              void* d_out, int out_size) {
    const float* x = (const float*)d_in[0];
    const float* w = (const float*)d_in[1];
    if (n_in >= 2 && in_sizes[0] < in_sizes[1]) {        // x is the big tensor
        x = (const float*)d_in[1];
        w = (const float*)d_in[0];
    }
    float* out = (float*)d_out;

    float* scratch = nullptr;
    cudaGetSymbolAddress((void**)&scratch, d_scratch);

    static bool attr_set = false;
    if (!attr_set) {
        cudaFuncSetAttribute(warp_interp_kernel,
                             cudaFuncAttributeMaxDynamicSharedMemorySize, SMEM_BYTES);
        attr_set = true;
    }

    setup_kernel<<<1, 1>>>();

    dim3 tb(32, 8);
    dim3 gT(T_DIM / 32, C_DIM / 32, B_DIM);
    transpose_btc_to_bct<<<gT, tb>>>(x, scratch);

    dim3 gW(C_DIM, B_DIM);
    warp_interp_kernel<<<gW, 256, SMEM_BYTES>>>(w, scratch);

    transpose_bct_to_btc<<<gT, tb>>>(scratch, out);
}

// round 13
// speedup vs baseline: 1.4390x; 1.0636x over previous
#include <cuda_runtime.h>
#include <math.h>

#define B_DIM 128
#define T_DIM 4096
#define C_DIM 64
#define N_KNOT 6

// -------- scratch & constants (no allocation allowed) --------
__device__ float d_LU[N_KNOT][N_KNOT];   // netlib sgetf2 packed L(unit)+U
__device__ float d_Uinv[N_KNOT];         // fl(1/U[k][k])
__device__ int   d_perm[N_KNOT];
__device__ float d_scratch[(size_t)B_DIM * C_DIM * T_DIM]; // [B,C,T], in-place

// reciprocal constants (correctly-rounded host folds, same as XLA's rewrite)
#define R819   (1.0f / 819.0f)
#define R6C    (1.0f / 6.0f)
#define R4914  (1.0f / 4914.0f)

// -------- setup: netlib sgetf2 (recip-scale + fma sger), fp32 --------
__global__ void setup_kernel() {
    if (threadIdx.x != 0 || blockIdx.x != 0) return;
    float A[N_KNOT][N_KNOT];
    for (int i = 0; i < N_KNOT; i++)
        for (int j = 0; j < N_KNOT; j++) A[i][j] = 0.0f;
    const float h = 819.0f;
    A[0][0] = -1.0f; A[0][1] = 2.0f; A[0][2] = -1.0f;
    for (int i = 1; i <= 4; i++) { A[i][i-1] = h; A[i][i] = 4.0f*h; A[i][i+1] = h; }
    A[5][3] = -1.0f; A[5][4] = 2.0f; A[5][5] = -1.0f;

    int ipiv[N_KNOT];
    for (int j = 0; j < N_KNOT; j++) {
        int p = j;
        float best = fabsf(A[j][j]);
        for (int i = j + 1; i < N_KNOT; i++) {
            float v = fabsf(A[i][j]);
            if (v > best) { best = v; p = i; }
        }
        ipiv[j] = p;
        if (p != j) {
            for (int k = 0; k < N_KNOT; k++) {
                float t = A[j][k]; A[j][k] = A[p][k]; A[p][k] = t;
            }
        }
        float r = __fdiv_rn(1.0f, A[j][j]);
        for (int i = j + 1; i < N_KNOT; i++)
            A[i][j] = __fmul_rn(A[i][j], r);
        for (int k = j + 1; k < N_KNOT; k++) {
            float temp = -A[j][k];
            for (int i = j + 1; i < N_KNOT; i++)
                A[i][k] = __fmaf_rn(A[i][j], temp, A[i][k]);
        }
    }
    int perm[N_KNOT];
    for (int i = 0; i < N_KNOT; i++) perm[i] = i;
    for (int j = 0; j < N_KNOT; j++) {
        int p = ipiv[j];
        int t = perm[j]; perm[j] = perm[p]; perm[p] = t;
    }
    for (int i = 0; i < N_KNOT; i++) {
        d_perm[i] = perm[i];
        for (int j = 0; j < N_KNOT; j++) d_LU[i][j] = A[i][j];
        d_Uinv[i] = __fdiv_rn(1.0f, A[i][i]);
    }
}

// -------- transpose [B,T,C] -> [B,C,T] --------
__global__ void transpose_btc_to_bct(const float* __restrict__ in, float* __restrict__ out) {
    __shared__ float tile[32][33];
    int b = blockIdx.z;
    int t0 = blockIdx.x * 32;
    int c0 = blockIdx.y * 32;
    int tx = threadIdx.x, ty = threadIdx.y;
    const float* inb = in + (size_t)b * T_DIM * C_DIM;
    float* outb = out + (size_t)b * T_DIM * C_DIM;
    #pragma unroll
    for (int i = 0; i < 32; i += 8)
        tile[ty + i][tx] = inb[(size_t)(t0 + ty + i) * C_DIM + (c0 + tx)];
    __syncthreads();
    #pragma unroll
    for (int i = 0; i < 32; i += 8)
        outb[(size_t)(c0 + ty + i) * T_DIM + (t0 + tx)] = tile[tx][ty + i];
}

// -------- transpose [B,C,T] -> [B,T,C] --------
__global__ void transpose_bct_to_btc(const float* __restrict__ in, float* __restrict__ out) {
    __shared__ float tile[32][33];
    int b = blockIdx.z;
    int t0 = blockIdx.x * 32;
    int c0 = blockIdx.y * 32;
    int tx = threadIdx.x, ty = threadIdx.y;
    const float* inb = in + (size_t)b * T_DIM * C_DIM;
    float* outb = out + (size_t)b * T_DIM * C_DIM;
    #pragma unroll
    for (int i = 0; i < 32; i += 8)
        tile[ty + i][tx] = inb[(size_t)(c0 + ty + i) * T_DIM + (t0 + tx)];
    __syncthreads();
    #pragma unroll
    for (int i = 0; i < 32; i += 8)
        outb[(size_t)(t0 + ty + i) * C_DIM + (c0 + tx)] = tile[tx][ty + i];
}

// -------- main per-series kernel (C1 numeric path; range-scatter fast search) --------
__global__ __launch_bounds__(256)
void warp_interp_kernel(const float* __restrict__ warps,
                        float* __restrict__ series /* [B,C,T], in-place */) {
    __shared__ float s_xp[T_DIM];
    __shared__ float s_fp[T_DIM];
    __shared__ unsigned short s_ins[T_DIM];       // 4096 fits in u16
    __shared__ float s_y[N_KNOT];
    __shared__ float s_M[N_KNOT];

    const int c = blockIdx.x;
    const int b = blockIdx.y;
    const int tid = threadIdx.x;
    float* row = series + ((size_t)b * C_DIM + c) * T_DIM;

    if (tid == 0) {
        float r[N_KNOT], y[N_KNOT];
        #pragma unroll
        for (int k = 0; k < N_KNOT; k++)
            r[k] = warps[((size_t)b * N_KNOT + k) * C_DIM + c];   // random_warps[b,k,c]
        #pragma unroll
        for (int k = 0; k < N_KNOT; k++)
            y[k] = __fmul_rn(819.0f * (float)k, r[k]);            // y = w*r

        // rhs[i] = (6*((y[i+1]-2*y[i]) + y[i-1])) * fl(1/819)
        float rhs[N_KNOT];
        rhs[0] = 0.0f; rhs[5] = 0.0f;
        #pragma unroll
        for (int i = 1; i <= 4; i++) {
            float t1 = __fmul_rn(2.0f, y[i]);
            float t2 = __fsub_rn(y[i + 1], t1);
            float t3 = __fadd_rn(t2, y[i - 1]);
            float t4 = __fmul_rn(6.0f, t3);
            rhs[i] = __fmul_rn(t4, R819);
        }

        // P*b gather, then axpy fwd (unit L) + axpy bwd with recip-mult diag
        float bb[N_KNOT];
        #pragma unroll
        for (int i = 0; i < N_KNOT; i++) bb[i] = rhs[d_perm[i]];
        #pragma unroll
        for (int k = 0; k < N_KNOT; k++) {
            if (bb[k] != 0.0f) {
                #pragma unroll
                for (int i = k + 1; i < N_KNOT; i++)
                    bb[i] = __fmaf_rn(-bb[k], d_LU[i][k], bb[i]);
            }
        }
        #pragma unroll
        for (int k = N_KNOT - 1; k >= 0; k--) {
            if (bb[k] != 0.0f) {
                bb[k] = __fmul_rn(bb[k], d_Uinv[k]);
                #pragma unroll
                for (int i = 0; i < k; i++)
                    bb[i] = __fmaf_rn(-bb[k], d_LU[i][k], bb[i]);
            }
        }
        #pragma unroll
        for (int k = 0; k < N_KNOT; k++) { s_y[k] = y[k]; s_M[k] = bb[k]; }
    }
    __syncthreads();

    // tw evaluator, frozen op order (XLA recip-mult constant rewrite)
    auto eval_tw = [&](int idx, float t) -> float {
        const float y0 = s_y[idx], y1 = s_y[idx + 1];
        const float M0 = s_M[idx], M1 = s_M[idx + 1];
        float a  = __fsub_rn(y1, y0);
        float bq = __fmul_rn(a, R819);
        float cq = __fmul_rn(2.0f, M0);
        float dq = __fadd_rn(cq, M1);
        float eq = __fmul_rn(819.0f, dq);
        float fq2 = __fmul_rn(eq, R6C);
        float c1 = __fsub_rn(bq, fq2);
        float g1 = __fmul_rn(t, c1);
        float s1 = __fadd_rn(y0, g1);
        float tt = __fmul_rn(t, t);
        float m02 = __fmul_rn(M0, 0.5f);
        float q1 = __fmul_rn(tt, m02);
        float s2 = __fadd_rn(s1, q1);
        float ttt = __fmul_rn(tt, t);
        float dm = __fsub_rn(M1, M0);
        float kk = __fmul_rn(dm, R4914);
        float q2 = __fmul_rn(ttt, kk);
        return __fadd_rn(s2, q2);
    };

    const float scale = __fdiv_rn(4095.0f, eval_tw(4, 819.0f));

    // ---- fill fp (strided, coalesced LDG) ----
    for (int j = tid; j < T_DIM; j += 256) s_fp[j] = row[j];

    // ---- fill xp: 16 consecutive per thread, mono check in registers ----
    const int j0 = tid * 16;
    float xv[16];
    #pragma unroll
    for (int k = 0; k < 16; k++) {
        const float xq = (float)(j0 + k);
        int idx = (int)__fmul_rn(xq, R819);
        idx = idx < 0 ? 0 : (idx > 4 ? 4 : idx);
        const float t = __fsub_rn(xq, 819.0f * (float)idx);
        float tw = eval_tw(idx, t);
        float xpv = __fmul_rn(scale, tw);
        xpv = fminf(fmaxf(xpv, 0.0f), 4095.0f);
        xv[k] = xpv;
        s_xp[j0 + k] = xpv;
    }
    int mono = 1;
    #pragma unroll
    for (int k = 0; k < 15; k++) mono &= (xv[k] <= xv[k + 1]);
    __syncthreads();
    if (j0 + 16 < T_DIM) mono &= (xv[15] <= s_xp[j0 + 16]);
    const int allmono = __syncthreads_and(mono);

    const float xp0 = s_xp[0],       xpN = s_xp[T_DIM - 1];
    const float fp0 = s_fp[0],       fpN = s_fp[T_DIM - 1];

    if (allmono) {
        // ---- FAST PATH (≡ scan-search for monotone xp; bit-matched R11/R12) ----
        // g[i] = ceil(xp[i]) nondecreasing; ins(q) = #{i: xp_i <= q} means
        // ins[q] = i exactly for q in [g[i-1], g[i]). Ranges partition [0,4096):
        // scatter with plain u16 stores — no atomics, no zeroing, no prefix scan.
        int gprev = (j0 == 0) ? 0 : (int)ceilf(s_xp[j0 - 1]);
        #pragma unroll
        for (int k = 0; k < 16; k++) {
            const int gk = (int)ceilf(xv[k]);
            for (int q = gprev; q < gk; q++)
                s_ins[q] = (unsigned short)(j0 + k);
            gprev = gk;
        }
        if (j0 + 16 == T_DIM) {                       // tail: q >= g[last] -> ins = 4096
            for (int q = gprev; q < T_DIM; q++)
                s_ins[q] = (unsigned short)T_DIM;
        }
        __syncthreads();

        // ---- interp: one u16 LDS lookup + 4 gathers per query ----
        for (int q = tid; q < T_DIM; q += 256) {
            const float fq = (float)q;
            int i = (int)s_ins[q];
            i = i < 1 ? 1 : (i > T_DIM - 1 ? T_DIM - 1 : i);

            const float x0 = s_xp[i - 1], x1 = s_xp[i];
            const float f0 = s_fp[i - 1], f1 = s_fp[i];
            const float dx = __fsub_rn(x1, x0);
            float f;
            if (fabsf(dx) <= 1.4210855e-14f) {
                f = f0;
            } else {
                const float df    = __fsub_rn(f1, f0);
                const float delta = __fsub_rn(fq, x0);
                const float ratio = __fdiv_rn(delta, dx);
                const float prod  = __fmul_rn(ratio, df);
                f = __fadd_rn(f0, prod);
            }
            if (fq < xp0) f = fp0;
            if (fq > xpN) f = fpN;
            row[q] = f;
        }
    } else {
        // ---- SLOW PATH: exact jnp scan replica per query ----
        for (int q = tid; q < T_DIM; q += 256) {
            const float fq = (float)q;
            int lo = 0, hi = T_DIM;
            #pragma unroll
            for (int s = 0; s < 13; s++) {
                const int mid = (lo + hi) >> 1;
                const bool go_left = fq < s_xp[mid];
                lo = go_left ? lo : mid;
                hi = go_left ? mid : hi;
            }
            int i = hi;
            i = i < 1 ? 1 : (i > T_DIM - 1 ? T_DIM - 1 : i);

            const float x0 = s_xp[i - 1], x1 = s_xp[i];
            const float f0 = s_fp[i - 1], f1 = s_fp[i];
            const float dx = __fsub_rn(x1, x0);
            float f;
            if (fabsf(dx) <= 1.4210855e-14f) {
                f = f0;
            } else {
                const float df    = __fsub_rn(f1, f0);
                const float delta = __fsub_rn(fq, x0);
                const float ratio = __fdiv_rn(delta, dx);
                const float prod  = __fmul_rn(ratio, df);
                f = __fadd_rn(f0, prod);
            }
            if (fq < xp0) f = fp0;
            if (fq > xpN) f = fpN;
            row[q] = f;
        }
    }
}

extern "C" void kernel_launch(void* const* d_in, const int* in_sizes, int n_in,
                              void* d_out, int out_size) {
    const float* x = (const float*)d_in[0];
    const float* w = (const float*)d_in[1];
    if (n_in >= 2 && in_sizes[0] < in_sizes[1]) {        // x is the big tensor
        x = (const float*)d_in[1];
        w = (const float*)d_in[0];
    }
    float* out = (float*)d_out;

    float* scratch = nullptr;
    cudaGetSymbolAddress((void**)&scratch, d_scratch);

    setup_kernel<<<1, 1>>>();

    dim3 tb(32, 8);
    dim3 gT(T_DIM / 32, C_DIM / 32, B_DIM);
    transpose_btc_to_bct<<<gT, tb>>>(x, scratch);

    dim3 gW(C_DIM, B_DIM);
    warp_interp_kernel<<<gW, 256>>>(w, scratch);

    transpose_bct_to_btc<<<gT, tb>>>(scratch, out);
}